// round 3
// baseline (speedup 1.0000x reference)
#include <cuda_runtime.h>
#include <cuda_bf16.h>

// RWSE encoder: diag(P^k) for k=1..16, then linear [16 -> 8].
// P = D^{-1} A, sparse (E=65536 edges over N=4096 nodes).
//
// Algorithm:
//   C_j := (P^T)^j  (row-major, N x N fp32), j = 1..8, via SpMM chain.
//   diag(P^k)[i] = C_k[i][i]                      for k = 1..8
//   diag(P^{j+8})[i] = sum_t C_j[t][i]*C_8[i][t]  for j = 1..8  (k = 9..16)
//   out[i][d] = b[d] + sum_k diag_k[i] * w[d][k]

#define NN 4096
#define EE 65536
#define NSLOT 128
#define WL 16
#define OD 8

// ---- static device scratch (no allocations allowed) ----
__device__ float g_C[8][(size_t)NN * NN];   // 512 MB: C_1 .. C_8
__device__ int   g_ei32[2 * EE];            // canonical int32 edge_index
__device__ int   g_degout[NN];
__device__ int   g_cnt[NN];
__device__ int   g_src[NN * NSLOT];
__device__ float g_val[NN * NSLOT];
__device__ float g_diag[WL * NN];           // diag[k-1][i]

// Canonicalize edge_index to int32, auto-detecting int32 vs int64 storage.
// int64 little-endian values in [0, 4096) have all-zero odd 32-bit words;
// OR of the first 64 odd words being 0 => int64 (P[false pos] ~ 4096^-64).
__global__ void k_convert(const int* __restrict__ raw, int E) {
    int acc = 0;
#pragma unroll
    for (int q = 1; q < 128; q += 2) acc |= raw[q];
    bool is64 = (acc == 0);
    int e = blockIdx.x * blockDim.x + threadIdx.x;
    if (e < 2 * E)
        g_ei32[e] = is64 ? (int)(((const long long*)raw)[e]) : raw[e];
}

// Zero everything that needs zeroing (C_1 scatter target, counters, diag).
__global__ void k_zero() {
    size_t i = (size_t)blockIdx.x * blockDim.x + threadIdx.x;  // up to 16.7M
    g_C[0][i] = 0.0f;
    if (i < NN) { g_cnt[i] = 0; g_degout[i] = 0; }
    if (i < (size_t)WL * NN) g_diag[i] = 0.0f;
}

// Out-degree (with edge multiplicity), matching .at[row].add(1.0).
__global__ void k_count(int E) {
    int e = blockIdx.x * blockDim.x + threadIdx.x;
    if (e < E) {
        int r = g_ei32[e];
        if (r >= 0 && r < NN) atomicAdd(&g_degout[r], 1);
    }
}

// Scatter edges into per-destination slot lists AND build C_1 = P^T directly:
// C_1[c][r] += v with v = 1/max(deg_out[r],1). Duplicate edges sum, matching
// the reference's .at[row, col].add(rw_values).
__global__ void k_scatter(int E) {
    int e = blockIdx.x * blockDim.x + threadIdx.x;
    if (e >= E) return;
    int r = g_ei32[e];
    int c = g_ei32[E + e];
    if (r < 0 || r >= NN || c < 0 || c >= NN) return;
    int d = g_degout[r]; if (d < 1) d = 1;
    float v = 1.0f / (float)d;
    int p = atomicAdd(&g_cnt[c], 1);
    if (p < NSLOT) { g_src[c * NSLOT + p] = r; g_val[c * NSLOT + p] = v; }
    atomicAdd(&g_C[0][(size_t)c * NN + r], v);
}

// SpMM: C_j[c][:] = sum over in-edges (r -> c): v * C_{j-1}[r][:]
// One block per output row c. 256 threads x 4 float4 = 4096 columns.
__global__ void __launch_bounds__(256) k_spmm(int j) {
    const float* __restrict__ in = g_C[j - 1];
    float* __restrict__ out = g_C[j];
    int c = blockIdx.x;
    int t = threadIdx.x;

    __shared__ int   s_src[NSLOT];
    __shared__ float s_val[NSLOT];
    int n = g_cnt[c]; if (n > NSLOT) n = NSLOT;
    if (t < n) { s_src[t] = g_src[c * NSLOT + t]; s_val[t] = g_val[c * NSLOT + t]; }
    __syncthreads();

    float4 a0 = make_float4(0.f, 0.f, 0.f, 0.f);
    float4 a1 = a0, a2 = a0, a3 = a0;

    for (int e = 0; e < n; e++) {
        const float4* row = (const float4*)(in + (size_t)s_src[e] * NN);
        float v = s_val[e];
        float4 x0 = __ldg(row + t);
        float4 x1 = __ldg(row + t + 256);
        float4 x2 = __ldg(row + t + 512);
        float4 x3 = __ldg(row + t + 768);
        a0.x += v * x0.x; a0.y += v * x0.y; a0.z += v * x0.z; a0.w += v * x0.w;
        a1.x += v * x1.x; a1.y += v * x1.y; a1.z += v * x1.z; a1.w += v * x1.w;
        a2.x += v * x2.x; a2.y += v * x2.y; a2.z += v * x2.z; a2.w += v * x2.w;
        a3.x += v * x3.x; a3.y += v * x3.y; a3.z += v * x3.z; a3.w += v * x3.w;
    }

    float4* o = (float4*)(out + (size_t)c * NN);
    __stcs(o + t, a0);
    __stcs(o + t + 256, a1);
    __stcs(o + t + 512, a2);
    __stcs(o + t + 768, a3);
}

// diag(P^k)[i] = C_k[i][i] for k = 1..8
__global__ void k_diag8() {
    int i = blockIdx.x * blockDim.x + threadIdx.x;
    if (i >= NN) return;
#pragma unroll
    for (int j = 0; j < 8; j++)
        g_diag[j * NN + i] = g_C[j][(size_t)i * NN + i];
}

// diag(P^{j+8})[i] = sum_t C_j[t][i] * C_8[i][t], for j = 1..8 (k = 9..16).
// 32x32 tiles: B = C_8[i-tile][t-tile] staged in smem (transposed access);
// A = C_j[t-tile][i-tile] read coalesced. grid = (N/32 i-tiles, N/32 t-tiles).
__global__ void __launch_bounds__(256) k_pair() {
    int i0 = blockIdx.x * 32;
    int t0 = blockIdx.y * 32;
    int tx = threadIdx.x;   // 0..31
    int ty = threadIdx.y;   // 0..7

    __shared__ float Bs[32][33];
#pragma unroll
    for (int q = 0; q < 4; q++) {
        int r = ty + 8 * q;
        Bs[r][tx] = g_C[7][(size_t)(i0 + r) * NN + t0 + tx];
    }
    __syncthreads();

    float part[8];
#pragma unroll
    for (int j = 0; j < 8; j++) {
        float p = 0.f;
#pragma unroll
        for (int q = 0; q < 4; q++) {
            int tt = ty + 8 * q;
            p += g_C[j][(size_t)(t0 + tt) * NN + i0 + tx] * Bs[tx][tt];
        }
        part[j] = p;
    }

    __shared__ float red[8][32];
#pragma unroll
    for (int j = 0; j < 8; j++) {
        __syncthreads();
        red[ty][tx] = part[j];
        __syncthreads();
        if (ty == 0) {
            float s = red[0][tx] + red[1][tx] + red[2][tx] + red[3][tx]
                    + red[4][tx] + red[5][tx] + red[6][tx] + red[7][tx];
            atomicAdd(&g_diag[(8 + j) * NN + i0 + tx], s);
        }
    }
}

// out[i][d] = b[d] + sum_k diag_k[i] * w[d][k]
__global__ void k_linear(const float* __restrict__ w, const float* __restrict__ b,
                         float* __restrict__ out) {
    int i = blockIdx.x * blockDim.x + threadIdx.x;
    if (i >= NN) return;
    float dv[WL];
#pragma unroll
    for (int k = 0; k < WL; k++) dv[k] = g_diag[k * NN + i];
#pragma unroll
    for (int d = 0; d < OD; d++) {
        float s = b[d];
#pragma unroll
        for (int k = 0; k < WL; k++) s += dv[k] * w[d * WL + k];
        out[i * OD + d] = s;
    }
}

extern "C" void kernel_launch(void* const* d_in, const int* in_sizes, int n_in,
                              void* d_out, int out_size) {
    const int* ei_raw = (const int*)d_in[0];           // edge_index [2, E], dtype detected on device
    int E = in_sizes[0] / 2;
    if (E > EE) E = EE;

    // Locate weight [OD*WL] and bias [OD] by element count (robust to whether
    // the num_nodes scalar is materialized as a device input).
    const float* w = nullptr;
    const float* b = nullptr;
    for (int i = 1; i < n_in; i++) {
        if (in_sizes[i] == OD * WL)      w = (const float*)d_in[i];
        else if (in_sizes[i] == OD)      b = (const float*)d_in[i];
    }
    if (!w) w = (const float*)d_in[n_in - 2];
    if (!b) b = (const float*)d_in[n_in - 1];

    float* out = (float*)d_out;                        // [N, 8] fp32

    k_convert<<<(2 * E + 255) / 256, 256>>>(ei_raw, E);
    k_zero<<<(NN * NN) / 256, 256>>>();
    k_count<<<(E + 255) / 256, 256>>>(E);
    k_scatter<<<(E + 255) / 256, 256>>>(E);
    for (int j = 1; j < 8; j++)
        k_spmm<<<NN, 256>>>(j);
    k_diag8<<<NN / 256, 256>>>();
    dim3 bb(32, 8), gg(NN / 32, NN / 32);
    k_pair<<<gg, bb>>>();
    k_linear<<<NN / 256, 256>>>(w, b, out);
}

// round 4
// speedup vs baseline: 1.0400x; 1.0400x over previous
#include <cuda_runtime.h>
#include <cuda_bf16.h>

// RWSE encoder: diag(P^k) for k=1..16, then linear [16 -> 8].
// P = D^{-1} A, sparse (E=65536 edges over N=4096 nodes).
//
//   C_p := (P^T)^p  dense row-major, p = 2..8.  C_2 built by 2-hop sparse
//   scatter; C_3..C_8 by 6 gather-SpMM steps.
//   diag(P^1)[i]  = self-loop weight sum (sparse)
//   diag(P^p)[i]  = C_p[i][i], p = 2..8
//   diag(P^9)[i]  = v_i * sum_{(i->t)} C_8[i,t]                (sparse)
//   diag(P^10)[i] = v_i * sum_{(i->m)} v_m sum_{(m->t)} C_8[i,t]
//   diag(P^{p+8})[i] = sum_t C_p[t,i]*C_8[i,t], p = 3..8       (dense pair)
//   out[i][d] = b[d] + sum_k diag_k[i] * w[d][k]

#define NN 4096
#define EE 65536
#define NSLOT 128
#define WL 16
#define OD 8

// ---- static device scratch (no allocations allowed) ----
__device__ float g_C[7][(size_t)NN * NN];   // 448 MB: C_2 .. C_8  (power p -> g_C[p-2])
__device__ int   g_ei32[2 * EE];
__device__ int   g_degout[NN];
__device__ int   g_cnt[NN];                 // in-edge counts  (by dest)
__device__ int   g_ocnt[NN];                // out-edge counts (by src)
__device__ int   g_src[NN * NSLOT];         // in-edge src lists
__device__ float g_val[NN * NSLOT];         // in-edge weights 1/deg(src)
__device__ int   g_odst[NN * NSLOT];        // out-edge dst lists
__device__ float g_diag[WL * NN];           // diag[k-1][i]

// Canonicalize edge_index to int32, auto-detecting int32 vs int64 storage.
__global__ void k_convert(const int* __restrict__ raw, int E) {
    int acc = 0;
#pragma unroll
    for (int q = 1; q < 128; q += 2) acc |= raw[q];
    bool is64 = (acc == 0);
    int e = blockIdx.x * blockDim.x + threadIdx.x;
    if (e < 2 * E)
        g_ei32[e] = is64 ? (int)(((const long long*)raw)[e]) : raw[e];
}

// Zero counters + diag (no dense matrix zeroing needed anymore).
__global__ void k_zero() {
    int i = blockIdx.x * blockDim.x + threadIdx.x;   // covers WL*NN
    g_diag[i] = 0.0f;
    if (i < NN) { g_cnt[i] = 0; g_ocnt[i] = 0; g_degout[i] = 0; }
}

__global__ void k_count(int E) {
    int e = blockIdx.x * blockDim.x + threadIdx.x;
    if (e < E) {
        int r = g_ei32[e];
        if (r >= 0 && r < NN) atomicAdd(&g_degout[r], 1);
    }
}

// Build in-edge lists (by dest), out-edge lists (by src), and diag(P^1) from
// self-loops. Duplicate edges keep multiplicity (matching .at[].add).
__global__ void k_scatter(int E) {
    int e = blockIdx.x * blockDim.x + threadIdx.x;
    if (e >= E) return;
    int r = g_ei32[e];
    int c = g_ei32[E + e];
    if (r < 0 || r >= NN || c < 0 || c >= NN) return;
    int d = g_degout[r]; if (d < 1) d = 1;
    float v = 1.0f / (float)d;
    int p = atomicAdd(&g_cnt[c], 1);
    if (p < NSLOT) { g_src[c * NSLOT + p] = r; g_val[c * NSLOT + p] = v; }
    int q = atomicAdd(&g_ocnt[r], 1);
    if (q < NSLOT) g_odst[r * NSLOT + q] = c;
    if (r == c) atomicAdd(&g_diag[r], v);            // diag(P^1)
}

// C_2[c][m] = sum_{(r->c)} v_rc * sum_{(m->r)} v_mr — two-hop scatter into a
// shared-memory row, then streamed out. One block per output row c.
__global__ void __launch_bounds__(256) k_build_c2() {
    __shared__ float srow[NN];
    int c = blockIdx.x, t = threadIdx.x;
    for (int q = t; q < NN; q += 256) srow[q] = 0.0f;
    __syncthreads();
    int n1 = g_cnt[c]; if (n1 > NSLOT) n1 = NSLOT;
    for (int e1 = 0; e1 < n1; e1++) {
        int r = g_src[c * NSLOT + e1];
        float v = g_val[c * NSLOT + e1];
        int n2 = g_cnt[r]; if (n2 > NSLOT) n2 = NSLOT;
        for (int e2 = t; e2 < n2; e2 += 256)
            atomicAdd(&srow[g_src[r * NSLOT + e2]], v * g_val[r * NSLOT + e2]);
    }
    __syncthreads();
    float4* o = (float4*)(g_C[0] + (size_t)c * NN);
    const float4* s = (const float4*)srow;
    for (int q = t; q < NN / 4; q += 256) __stcs(o + q, s[q]);
}

// SpMM: C_p[c][:] = sum_{(r->c)} v * C_{p-1}[r][:].  One block per output row.
// C_8 stored with regular stores (re-read 7x by pairing -> keep L2-resident);
// intermediates stored evict-first.
__global__ void __launch_bounds__(256) k_spmm(int p) {
    const float* __restrict__ in = g_C[p - 3];
    float* __restrict__ out = g_C[p - 2];
    int c = blockIdx.x;
    int t = threadIdx.x;

    __shared__ int   s_src[NSLOT];
    __shared__ float s_val[NSLOT];
    int n = g_cnt[c]; if (n > NSLOT) n = NSLOT;
    if (t < n) { s_src[t] = g_src[c * NSLOT + t]; s_val[t] = g_val[c * NSLOT + t]; }
    __syncthreads();

    float4 a0 = make_float4(0.f, 0.f, 0.f, 0.f);
    float4 a1 = a0, a2 = a0, a3 = a0;

    for (int e = 0; e < n; e++) {
        const float4* row = (const float4*)(in + (size_t)s_src[e] * NN);
        float v = s_val[e];
        float4 x0 = __ldg(row + t);
        float4 x1 = __ldg(row + t + 256);
        float4 x2 = __ldg(row + t + 512);
        float4 x3 = __ldg(row + t + 768);
        a0.x += v * x0.x; a0.y += v * x0.y; a0.z += v * x0.z; a0.w += v * x0.w;
        a1.x += v * x1.x; a1.y += v * x1.y; a1.z += v * x1.z; a1.w += v * x1.w;
        a2.x += v * x2.x; a2.y += v * x2.y; a2.z += v * x2.z; a2.w += v * x2.w;
        a3.x += v * x3.x; a3.y += v * x3.y; a3.z += v * x3.z; a3.w += v * x3.w;
    }

    float4* o = (float4*)(out + (size_t)c * NN);
    if (p == 8) {
        o[t] = a0; o[t + 256] = a1; o[t + 512] = a2; o[t + 768] = a3;
    } else {
        __stcs(o + t, a0);
        __stcs(o + t + 256, a1);
        __stcs(o + t + 512, a2);
        __stcs(o + t + 768, a3);
    }
}

// diag(P^p)[i] = C_p[i][i], p = 2..8
__global__ void k_diag_direct() {
    int i = blockIdx.x * blockDim.x + threadIdx.x;
    if (i >= NN) return;
#pragma unroll
    for (int p = 2; p <= 8; p++)
        g_diag[(p - 1) * NN + i] = g_C[p - 2][(size_t)i * NN + i];
}

// k=9, k=10 via sparse walks against C_8's row i (held in smem).
__global__ void __launch_bounds__(256) k_pair_sparse() {
    __shared__ float srow[NN];
    __shared__ float acc9, acc10;
    int i = blockIdx.x, t = threadIdx.x;
    const float* c8 = g_C[6] + (size_t)i * NN;
    for (int q = t; q < NN; q += 256) srow[q] = c8[q];
    if (t == 0) { acc9 = 0.f; acc10 = 0.f; }
    __syncthreads();

    int d = g_degout[i]; if (d < 1) d = 1;
    float vi = 1.0f / (float)d;
    int no = g_ocnt[i]; if (no > NSLOT) no = NSLOT;

    float p9 = 0.f, p10 = 0.f;
    for (int e1 = t; e1 < no; e1 += 256) p9 += srow[g_odst[i * NSLOT + e1]];
    for (int e1 = 0; e1 < no; e1++) {
        int m = g_odst[i * NSLOT + e1];
        int dm = g_degout[m]; if (dm < 1) dm = 1;
        float vm = 1.0f / (float)dm;
        int nm = g_ocnt[m]; if (nm > NSLOT) nm = NSLOT;
        float s = 0.f;
        for (int e2 = t; e2 < nm; e2 += 256) s += srow[g_odst[m * NSLOT + e2]];
        p10 += vm * s;
    }
#pragma unroll
    for (int off = 16; off > 0; off >>= 1) {
        p9  += __shfl_down_sync(0xffffffffu, p9, off);
        p10 += __shfl_down_sync(0xffffffffu, p10, off);
    }
    if ((t & 31) == 0) { atomicAdd(&acc9, p9); atomicAdd(&acc10, p10); }
    __syncthreads();
    if (t == 0) { g_diag[8 * NN + i] = vi * acc9; g_diag[9 * NN + i] = vi * acc10; }
}

// diag(P^{p+8})[i] = sum_t C_p[t,i] * C_8[i,t], p = 3..8 (k = 11..16).
// 32x32 tiles: C_8 tile staged/transposed in smem; C_p read coalesced.
__global__ void __launch_bounds__(256) k_pair() {
    int i0 = blockIdx.x * 32;
    int t0 = blockIdx.y * 32;
    int tx = threadIdx.x;   // 0..31
    int ty = threadIdx.y;   // 0..7

    __shared__ float Bs[32][33];
#pragma unroll
    for (int q = 0; q < 4; q++) {
        int r = ty + 8 * q;
        Bs[r][tx] = g_C[6][(size_t)(i0 + r) * NN + t0 + tx];
    }
    __syncthreads();

    float part[6];
#pragma unroll
    for (int j = 0; j < 6; j++) {                      // j -> power p = j+3
        float p = 0.f;
#pragma unroll
        for (int q = 0; q < 4; q++) {
            int tt = ty + 8 * q;
            p += g_C[j + 1][(size_t)(t0 + tt) * NN + i0 + tx] * Bs[tx][tt];
        }
        part[j] = p;
    }

    __shared__ float red[8][32];
#pragma unroll
    for (int j = 0; j < 6; j++) {
        __syncthreads();
        red[ty][tx] = part[j];
        __syncthreads();
        if (ty == 0) {
            float s = red[0][tx] + red[1][tx] + red[2][tx] + red[3][tx]
                    + red[4][tx] + red[5][tx] + red[6][tx] + red[7][tx];
            atomicAdd(&g_diag[(j + 10) * NN + i0 + tx], s);
        }
    }
}

// out[i][d] = b[d] + sum_k diag_k[i] * w[d][k]
__global__ void k_linear(const float* __restrict__ w, const float* __restrict__ b,
                         float* __restrict__ out) {
    int i = blockIdx.x * blockDim.x + threadIdx.x;
    if (i >= NN) return;
    float dv[WL];
#pragma unroll
    for (int k = 0; k < WL; k++) dv[k] = g_diag[k * NN + i];
#pragma unroll
    for (int d = 0; d < OD; d++) {
        float s = b[d];
#pragma unroll
        for (int k = 0; k < WL; k++) s += dv[k] * w[d * WL + k];
        out[i * OD + d] = s;
    }
}

extern "C" void kernel_launch(void* const* d_in, const int* in_sizes, int n_in,
                              void* d_out, int out_size) {
    const int* ei_raw = (const int*)d_in[0];           // edge_index [2, E]
    int E = in_sizes[0] / 2;
    if (E > EE) E = EE;

    const float* w = nullptr;
    const float* b = nullptr;
    for (int i = 1; i < n_in; i++) {
        if (in_sizes[i] == OD * WL)      w = (const float*)d_in[i];
        else if (in_sizes[i] == OD)      b = (const float*)d_in[i];
    }
    if (!w) w = (const float*)d_in[n_in - 2];
    if (!b) b = (const float*)d_in[n_in - 1];

    float* out = (float*)d_out;                        // [N, 8] fp32

    k_convert<<<(2 * E + 255) / 256, 256>>>(ei_raw, E);
    k_zero<<<(WL * NN) / 256, 256>>>();
    k_count<<<(E + 255) / 256, 256>>>(E);
    k_scatter<<<(E + 255) / 256, 256>>>(E);
    k_build_c2<<<NN, 256>>>();
    for (int p = 3; p <= 8; p++)
        k_spmm<<<NN, 256>>>(p);
    k_diag_direct<<<NN / 256, 256>>>();
    k_pair_sparse<<<NN, 256>>>();
    dim3 bb(32, 8), gg(NN / 32, NN / 32);
    k_pair<<<gg, bb>>>();
    k_linear<<<NN / 256, 256>>>(w, b, out);
}

// round 6
// speedup vs baseline: 1.0880x; 1.0462x over previous
#include <cuda_runtime.h>
#include <cuda_bf16.h>
#include <cuda_fp16.h>

// RWSE encoder: diag(P^k) for k=1..16, then linear [16 -> 8].
// P = D^{-1} A, sparse (E=65536 edges over N=4096 nodes).
//
//   C_p := (P^T)^p, p = 2..7 stored fp16 (32 MB each), C_8 stored fp32.
//   Chain: C_2 by 2-hop sparse scatter; C_3..C_8 by gather-SpMM (fp32 accum).
//   diag(P^1): self-loops (sparse).  diag(P^p), p=2..8: extracted from fp32
//   accumulators BEFORE fp16 quantization.  k=9,10: sparse walks vs C_8 rows.
//   k=11..16: diag(P^{p+8})[i] = sum_t C_p[t,i]*C_8[i,t], p=3..8.
//   out[i][d] = b[d] + sum_k diag_k[i] * w[d][k]

#define NN 4096
#define EE 65536
#define NSLOT 128
#define WL 16
#define OD 8

// ---- static device scratch (no allocations allowed) ----
__device__ __half g_Ch[6][(size_t)NN * NN];  // 192 MB: C_2..C_7 (p -> g_Ch[p-2])
__device__ float  g_C8[(size_t)NN * NN];     //  64 MB: C_8 fp32
__device__ int    g_ei32[2 * EE];
__device__ int    g_degout[NN];
__device__ int    g_cnt[NN];                 // in-edge counts  (by dest)
__device__ int    g_ocnt[NN];                // out-edge counts (by src)
__device__ int    g_src[NN * NSLOT];         // in-edge src lists
__device__ float  g_val[NN * NSLOT];         // in-edge weights 1/deg(src)
__device__ int    g_odst[NN * NSLOT];        // out-edge dst lists
__device__ float  g_diag[WL * NN];           // diag[k-1][i], fp32

// Fused: edge_index canonicalization (int32/int64 auto-detect) + zeroing.
__global__ void k_init(const int* __restrict__ raw, int E) {
    int acc = 0;
#pragma unroll
    for (int q = 1; q < 128; q += 2) acc |= raw[q];
    bool is64 = (acc == 0);
    int e = blockIdx.x * blockDim.x + threadIdx.x;
    if (e < 2 * E)
        g_ei32[e] = is64 ? (int)(((const long long*)raw)[e]) : raw[e];
    if (e < WL * NN) g_diag[e] = 0.0f;
    if (e < NN) { g_cnt[e] = 0; g_ocnt[e] = 0; g_degout[e] = 0; }
}

__global__ void k_count(int E) {
    int e = blockIdx.x * blockDim.x + threadIdx.x;
    if (e < E) {
        int r = g_ei32[e];
        if (r >= 0 && r < NN) atomicAdd(&g_degout[r], 1);
    }
}

// Build in/out edge lists and diag(P^1) from self-loops.
__global__ void k_scatter(int E) {
    int e = blockIdx.x * blockDim.x + threadIdx.x;
    if (e >= E) return;
    int r = g_ei32[e];
    int c = g_ei32[E + e];
    if (r < 0 || r >= NN || c < 0 || c >= NN) return;
    int d = g_degout[r]; if (d < 1) d = 1;
    float v = 1.0f / (float)d;
    int p = atomicAdd(&g_cnt[c], 1);
    if (p < NSLOT) { g_src[c * NSLOT + p] = r; g_val[c * NSLOT + p] = v; }
    int q = atomicAdd(&g_ocnt[r], 1);
    if (q < NSLOT) g_odst[r * NSLOT + q] = c;
    if (r == c) atomicAdd(&g_diag[r], v);            // diag(P^1)
}

// C_2[c][m] via 2-hop scatter into a smem fp32 row; diag(P^2) taken in fp32,
// row stored quantized to fp16.
__global__ void __launch_bounds__(256) k_build_c2() {
    __shared__ float srow[NN];
    int c = blockIdx.x, t = threadIdx.x;
    for (int q = t; q < NN; q += 256) srow[q] = 0.0f;
    __syncthreads();
    int n1 = g_cnt[c]; if (n1 > NSLOT) n1 = NSLOT;
    for (int e1 = 0; e1 < n1; e1++) {
        int r = g_src[c * NSLOT + e1];
        float v = g_val[c * NSLOT + e1];
        int n2 = g_cnt[r]; if (n2 > NSLOT) n2 = NSLOT;
        for (int e2 = t; e2 < n2; e2 += 256)
            atomicAdd(&srow[g_src[r * NSLOT + e2]], v * g_val[r * NSLOT + e2]);
    }
    __syncthreads();
    if (t == 0) g_diag[NN + c] = srow[c];            // diag(P^2), fp32
    __half2* o = (__half2*)(g_Ch[0] + (size_t)c * NN);
    for (int q = t; q < NN / 2; q += 256)
        o[q] = __floats2half2_rn(srow[2 * q], srow[2 * q + 1]);
}

// SpMM: C_p[c][:] = sum_{(r->c)} v * C_{p-1}[r][:].  fp16 gather, fp32 accum.
// Thread t owns columns [8t,8t+8) and [2048+8t, 2048+8t+8).
// diag(P^p) extracted from the fp32 accumulator before quantization.
__global__ void __launch_bounds__(256) k_spmm(int p) {
    const __half* __restrict__ in = g_Ch[p - 3];
    int c = blockIdx.x;
    int t = threadIdx.x;

    __shared__ int   s_src[NSLOT];
    __shared__ float s_val[NSLOT];
    int n = g_cnt[c]; if (n > NSLOT) n = NSLOT;
    if (t < n) { s_src[t] = g_src[c * NSLOT + t]; s_val[t] = g_val[c * NSLOT + t]; }
    __syncthreads();

    float acc[16];
#pragma unroll
    for (int s = 0; s < 16; s++) acc[s] = 0.0f;

    for (int e = 0; e < n; e++) {
        const uint4* row = (const uint4*)(in + (size_t)s_src[e] * NN);
        float v = s_val[e];
        uint4 u0 = __ldg(row + t);
        uint4 u1 = __ldg(row + t + 256);
        const __half2* h0 = (const __half2*)&u0;
        const __half2* h1 = (const __half2*)&u1;
#pragma unroll
        for (int q = 0; q < 4; q++) {
            float2 f0 = __half22float2(h0[q]);
            float2 f1 = __half22float2(h1[q]);
            acc[2 * q]         += v * f0.x;
            acc[2 * q + 1]     += v * f0.y;
            acc[8 + 2 * q]     += v * f1.x;
            acc[8 + 2 * q + 1] += v * f1.y;
        }
    }

    int base0 = 8 * t, base1 = 2048 + 8 * t;
    if (c >= base0 && c < base0 + 8)
        g_diag[(p - 1) * NN + c] = acc[c - base0];
    if (c >= base1 && c < base1 + 8)
        g_diag[(p - 1) * NN + c] = acc[8 + (c - base1)];

    if (p <= 7) {
        __half2 hh[8];
#pragma unroll
        for (int q = 0; q < 4; q++) {
            hh[q]     = __floats2half2_rn(acc[2 * q],     acc[2 * q + 1]);
            hh[4 + q] = __floats2half2_rn(acc[8 + 2 * q], acc[8 + 2 * q + 1]);
        }
        uint4* o = (uint4*)(g_Ch[p - 2] + (size_t)c * NN);
        o[t]       = *(uint4*)&hh[0];
        o[t + 256] = *(uint4*)&hh[4];
    } else {
        float4* o = (float4*)(g_C8 + (size_t)c * NN);
        o[2 * t]           = make_float4(acc[0],  acc[1],  acc[2],  acc[3]);
        o[2 * t + 1]       = make_float4(acc[4],  acc[5],  acc[6],  acc[7]);
        o[512 + 2 * t]     = make_float4(acc[8],  acc[9],  acc[10], acc[11]);
        o[512 + 2 * t + 1] = make_float4(acc[12], acc[13], acc[14], acc[15]);
    }
}

// k=9, k=10 via sparse walks against C_8's row i (held in smem).
__global__ void __launch_bounds__(256) k_pair_sparse() {
    __shared__ float srow[NN];
    __shared__ float acc9, acc10;
    int i = blockIdx.x, t = threadIdx.x;
    const float* c8 = g_C8 + (size_t)i * NN;
    for (int q = t; q < NN; q += 256) srow[q] = c8[q];
    if (t == 0) { acc9 = 0.f; acc10 = 0.f; }
    __syncthreads();

    int d = g_degout[i]; if (d < 1) d = 1;
    float vi = 1.0f / (float)d;
    int no = g_ocnt[i]; if (no > NSLOT) no = NSLOT;

    float p9 = 0.f, p10 = 0.f;
    for (int e1 = t; e1 < no; e1 += 256) p9 += srow[g_odst[i * NSLOT + e1]];
    for (int e1 = 0; e1 < no; e1++) {
        int m = g_odst[i * NSLOT + e1];
        int dm = g_degout[m]; if (dm < 1) dm = 1;
        float vm = 1.0f / (float)dm;
        int nm = g_ocnt[m]; if (nm > NSLOT) nm = NSLOT;
        float s = 0.f;
        for (int e2 = t; e2 < nm; e2 += 256) s += srow[g_odst[m * NSLOT + e2]];
        p10 += vm * s;
    }
#pragma unroll
    for (int off = 16; off > 0; off >>= 1) {
        p9  += __shfl_down_sync(0xffffffffu, p9, off);
        p10 += __shfl_down_sync(0xffffffffu, p10, off);
    }
    if ((t & 31) == 0) { atomicAdd(&acc9, p9); atomicAdd(&acc10, p10); }
    __syncthreads();
    if (t == 0) { g_diag[8 * NN + i] = vi * acc9; g_diag[9 * NN + i] = vi * acc10; }
}

// diag(P^{p+8})[i] = sum_t C_p[t,i] * C_8[i,t], p = 3..8 (k = 11..16).
// C_8 tile staged/transposed in smem (fp32); C_p read coalesced (fp16 for
// p<=7, fp32 for p=8). fp16 quantization averages out over the 4096-term dot.
__global__ void __launch_bounds__(256) k_pair() {
    int i0 = blockIdx.x * 32;
    int t0 = blockIdx.y * 32;
    int tx = threadIdx.x;   // 0..31
    int ty = threadIdx.y;   // 0..7

    __shared__ float Bs[32][33];
#pragma unroll
    for (int q = 0; q < 4; q++) {
        int r = ty + 8 * q;
        Bs[r][tx] = g_C8[(size_t)(i0 + r) * NN + t0 + tx];
    }
    __syncthreads();

    float part[6];
#pragma unroll
    for (int j = 0; j < 6; j++) {                      // j -> power p = j+3
        float p = 0.f;
#pragma unroll
        for (int q = 0; q < 4; q++) {
            int tt = ty + 8 * q;
            float a = (j < 5)
                ? __half2float(g_Ch[j + 1][(size_t)(t0 + tt) * NN + i0 + tx])
                : g_C8[(size_t)(t0 + tt) * NN + i0 + tx];
            p += a * Bs[tx][tt];
        }
        part[j] = p;
    }

    __shared__ float red[8][32];
#pragma unroll
    for (int j = 0; j < 6; j++) {
        __syncthreads();
        red[ty][tx] = part[j];
        __syncthreads();
        if (ty == 0) {
            float s = red[0][tx] + red[1][tx] + red[2][tx] + red[3][tx]
                    + red[4][tx] + red[5][tx] + red[6][tx] + red[7][tx];
            atomicAdd(&g_diag[(j + 10) * NN + i0 + tx], s);
        }
    }
}

// out[i][d] = b[d] + sum_k diag_k[i] * w[d][k]
__global__ void k_linear(const float* __restrict__ w, const float* __restrict__ b,
                         float* __restrict__ out) {
    int i = blockIdx.x * blockDim.x + threadIdx.x;
    if (i >= NN) return;
    float dv[WL];
#pragma unroll
    for (int k = 0; k < WL; k++) dv[k] = g_diag[k * NN + i];
#pragma unroll
    for (int d = 0; d < OD; d++) {
        float s = b[d];
#pragma unroll
        for (int k = 0; k < WL; k++) s += dv[k] * w[d * WL + k];
        out[i * OD + d] = s;
    }
}

extern "C" void kernel_launch(void* const* d_in, const int* in_sizes, int n_in,
                              void* d_out, int out_size) {
    const int* ei_raw = (const int*)d_in[0];           // edge_index [2, E]
    int E = in_sizes[0] / 2;
    if (E > EE) E = EE;

    const float* w = nullptr;
    const float* b = nullptr;
    for (int i = 1; i < n_in; i++) {
        if (in_sizes[i] == OD * WL)      w = (const float*)d_in[i];
        else if (in_sizes[i] == OD)      b = (const float*)d_in[i];
    }
    if (!w) w = (const float*)d_in[n_in - 2];
    if (!b) b = (const float*)d_in[n_in - 1];

    float* out = (float*)d_out;                        // [N, 8] fp32

    int init_elems = 2 * E > WL * NN ? 2 * E : WL * NN;
    k_init<<<(init_elems + 255) / 256, 256>>>(ei_raw, E);
    k_count<<<(E + 255) / 256, 256>>>(E);
    k_scatter<<<(E + 255) / 256, 256>>>(E);
    k_build_c2<<<NN, 256>>>();                          // profiled slot (#4)
    for (int p = 3; p <= 8; p++)
        k_spmm<<<NN, 256>>>(p);
    k_pair_sparse<<<NN, 256>>>();
    dim3 bb(32, 8), gg(NN / 32, NN / 32);
    k_pair<<<gg, bb>>>();
    k_linear<<<NN / 256, 256>>>(w, b, out);
}

// round 7
// speedup vs baseline: 1.2579x; 1.1561x over previous
#include <cuda_runtime.h>
#include <cuda_bf16.h>
#include <cuda_fp16.h>

// RWSE encoder: diag(P^k) for k=1..16, then linear [16 -> 8].
// P = D^{-1} A, sparse (E=65536 edges over N=4096 nodes).
//
//   diag(P^1), diag(P^2): O(deg^2) sparse per-node kernel.
//   C_3 built directly by 3-hop sparse scatter (fp32 smem row, fp16 store).
//   C_4..C_8 by 5 gather-SpMM steps (fp16 in, fp32 accum; C_8 kept fp32).
//   diag(P^p), p=3..8: extracted from fp32 accumulators pre-quantization.
//   k=9,10: sparse walks vs C_8 rows.  k=11..16: diag(P^{p+8})[i] =
//   sum_t C_p[t,i]*C_8[i,t], p=3..8.  out = diag @ w^T + b.

#define NN 4096
#define EE 65536
#define NSLOT 128
#define WL 16
#define OD 8

// ---- static device scratch (no allocations allowed) ----
__device__ __half g_Ch[5][(size_t)NN * NN];  // 160 MB: C_3..C_7 (p -> g_Ch[p-3])
__device__ float  g_C8[(size_t)NN * NN];     //  64 MB: C_8 fp32
__device__ int    g_ei32[2 * EE];
__device__ int    g_degout[NN];
__device__ int    g_cnt[NN];                 // in-edge counts  (by dest)
__device__ int    g_ocnt[NN];                // out-edge counts (by src)
__device__ int    g_src[NN * NSLOT];         // in-edge src lists
__device__ int    g_odst[NN * NSLOT];        // out-edge dst lists
__device__ float  g_diag[WL * NN];           // diag[k-1][i], fp32

__device__ __forceinline__ float inv_deg(int node) {
    int d = g_degout[node]; if (d < 1) d = 1;
    return 1.0f / (float)d;
}

// Fused: edge_index canonicalization (int32/int64 auto-detect) + zeroing.
__global__ void k_init(const int* __restrict__ raw, int E) {
    int acc = 0;
#pragma unroll
    for (int q = 1; q < 128; q += 2) acc |= raw[q];
    bool is64 = (acc == 0);
    int e = blockIdx.x * blockDim.x + threadIdx.x;
    if (e < 2 * E)
        g_ei32[e] = is64 ? (int)(((const long long*)raw)[e]) : raw[e];
    if (e < WL * NN) g_diag[e] = 0.0f;
    if (e < NN) { g_cnt[e] = 0; g_ocnt[e] = 0; g_degout[e] = 0; }
}

// Degree counting + adjacency-list build in one pass (weights derived later).
__global__ void k_scatter(int E) {
    int e = blockIdx.x * blockDim.x + threadIdx.x;
    if (e >= E) return;
    int r = g_ei32[e];
    int c = g_ei32[E + e];
    if (r < 0 || r >= NN || c < 0 || c >= NN) return;
    atomicAdd(&g_degout[r], 1);
    int p = atomicAdd(&g_cnt[c], 1);
    if (p < NSLOT) g_src[c * NSLOT + p] = r;
    int q = atomicAdd(&g_ocnt[r], 1);
    if (q < NSLOT) g_odst[r * NSLOT + q] = c;
}

// C_3[c][m] via 3-hop scatter into a smem fp32 row. Warp w handles hop-2
// edge e2 (strided by 8), lanes handle hop-3 edges. diag(P^3) in fp32.
__global__ void __launch_bounds__(256) k_build_c3() {
    __shared__ float srow[NN];
    int c = blockIdx.x, t = threadIdx.x;
    int w = t >> 5, lane = t & 31;
    float4* sz = (float4*)srow;
    for (int q = t; q < NN / 4; q += 256) sz[q] = make_float4(0.f, 0.f, 0.f, 0.f);
    __syncthreads();

    int n1 = g_cnt[c]; if (n1 > NSLOT) n1 = NSLOT;
    for (int e1 = 0; e1 < n1; e1++) {
        int r1 = g_src[c * NSLOT + e1];
        float v1 = inv_deg(r1);
        int n2 = g_cnt[r1]; if (n2 > NSLOT) n2 = NSLOT;
        for (int e2 = w; e2 < n2; e2 += 8) {
            int r2 = g_src[r1 * NSLOT + e2];
            float v12 = v1 * inv_deg(r2);
            int n3 = g_cnt[r2]; if (n3 > NSLOT) n3 = NSLOT;
            for (int e3 = lane; e3 < n3; e3 += 32) {
                int r3 = g_src[r2 * NSLOT + e3];
                atomicAdd(&srow[r3], v12 * inv_deg(r3));
            }
        }
    }
    __syncthreads();
    if (t == 0) g_diag[2 * NN + c] = srow[c];        // diag(P^3)
    __half2* o = (__half2*)(g_Ch[0] + (size_t)c * NN);
    for (int q = t; q < NN / 2; q += 256)
        o[q] = __floats2half2_rn(srow[2 * q], srow[2 * q + 1]);
}

// SpMM: C_p[c][:] = sum_{(r->c)} v * C_{p-1}[r][:].  fp16 gather, fp32 accum.
// Thread t owns columns [8t,8t+8) and [2048+8t, 2048+8t+8).
__global__ void __launch_bounds__(256) k_spmm(int p) {
    const __half* __restrict__ in = g_Ch[p - 4];
    int c = blockIdx.x;
    int t = threadIdx.x;

    __shared__ int   s_src[NSLOT];
    __shared__ float s_val[NSLOT];
    int n = g_cnt[c]; if (n > NSLOT) n = NSLOT;
    if (t < n) {
        int r = g_src[c * NSLOT + t];
        s_src[t] = r;
        s_val[t] = inv_deg(r);
    }
    __syncthreads();

    float acc[16];
#pragma unroll
    for (int s = 0; s < 16; s++) acc[s] = 0.0f;

#pragma unroll 2
    for (int e = 0; e < n; e++) {
        const uint4* row = (const uint4*)(in + (size_t)s_src[e] * NN);
        float v = s_val[e];
        uint4 u0 = __ldg(row + t);
        uint4 u1 = __ldg(row + t + 256);
        const __half2* h0 = (const __half2*)&u0;
        const __half2* h1 = (const __half2*)&u1;
#pragma unroll
        for (int q = 0; q < 4; q++) {
            float2 f0 = __half22float2(h0[q]);
            float2 f1 = __half22float2(h1[q]);
            acc[2 * q]         += v * f0.x;
            acc[2 * q + 1]     += v * f0.y;
            acc[8 + 2 * q]     += v * f1.x;
            acc[8 + 2 * q + 1] += v * f1.y;
        }
    }

    int base0 = 8 * t, base1 = 2048 + 8 * t;
    if (c >= base0 && c < base0 + 8)
        g_diag[(p - 1) * NN + c] = acc[c - base0];
    if (c >= base1 && c < base1 + 8)
        g_diag[(p - 1) * NN + c] = acc[8 + (c - base1)];

    if (p <= 7) {
        __half2 hh[8];
#pragma unroll
        for (int q = 0; q < 4; q++) {
            hh[q]     = __floats2half2_rn(acc[2 * q],     acc[2 * q + 1]);
            hh[4 + q] = __floats2half2_rn(acc[8 + 2 * q], acc[8 + 2 * q + 1]);
        }
        uint4* o = (uint4*)(g_Ch[p - 3] + (size_t)c * NN);
        o[t]       = *(uint4*)&hh[0];
        o[t + 256] = *(uint4*)&hh[4];
    } else {
        float4* o = (float4*)(g_C8 + (size_t)c * NN);
        o[2 * t]           = make_float4(acc[0],  acc[1],  acc[2],  acc[3]);
        o[2 * t + 1]       = make_float4(acc[4],  acc[5],  acc[6],  acc[7]);
        o[512 + 2 * t]     = make_float4(acc[8],  acc[9],  acc[10], acc[11]);
        o[512 + 2 * t + 1] = make_float4(acc[12], acc[13], acc[14], acc[15]);
    }
}

// diag(P^1)[i] = v_i * mult(i->i);  diag(P^2)[i] = v_i * sum_{e2 in in(i),
// src=m} v_m * mult(i->m).  One warp per node, O(deg^2) scans.
__global__ void k_diag12() {
    int i = blockIdx.x * 8 + (threadIdx.x >> 5);
    int lane = threadIdx.x & 31;
    if (i >= NN) return;
    float vi = inv_deg(i);
    int no = g_ocnt[i]; if (no > NSLOT) no = NSLOT;
    int ni = g_cnt[i];  if (ni > NSLOT) ni = NSLOT;

    float d1 = 0.f, d2 = 0.f;
    for (int e = lane; e < no; e += 32)
        if (g_odst[i * NSLOT + e] == i) d1 += 1.0f;
    for (int e2 = lane; e2 < ni; e2 += 32) {
        int m = g_src[i * NSLOT + e2];
        int cnt = 0;
        for (int e1 = 0; e1 < no; e1++)
            if (g_odst[i * NSLOT + e1] == m) cnt++;
        d2 += inv_deg(m) * (float)cnt;
    }
#pragma unroll
    for (int off = 16; off > 0; off >>= 1) {
        d1 += __shfl_down_sync(0xffffffffu, d1, off);
        d2 += __shfl_down_sync(0xffffffffu, d2, off);
    }
    if (lane == 0) {
        g_diag[i] = vi * d1;
        g_diag[NN + i] = vi * d2;
    }
}

// k=9, k=10 via sparse walks against C_8's row i (held in smem).
__global__ void __launch_bounds__(256) k_pair_sparse() {
    __shared__ float srow[NN];
    __shared__ float acc9, acc10;
    int i = blockIdx.x, t = threadIdx.x;
    const float* c8 = g_C8 + (size_t)i * NN;
    for (int q = t; q < NN; q += 256) srow[q] = c8[q];
    if (t == 0) { acc9 = 0.f; acc10 = 0.f; }
    __syncthreads();

    float vi = inv_deg(i);
    int no = g_ocnt[i]; if (no > NSLOT) no = NSLOT;

    float p9 = 0.f, p10 = 0.f;
    for (int e1 = t; e1 < no; e1 += 256) p9 += srow[g_odst[i * NSLOT + e1]];
    for (int e1 = 0; e1 < no; e1++) {
        int m = g_odst[i * NSLOT + e1];
        float vm = inv_deg(m);
        int nm = g_ocnt[m]; if (nm > NSLOT) nm = NSLOT;
        float s = 0.f;
        for (int e2 = t; e2 < nm; e2 += 256) s += srow[g_odst[m * NSLOT + e2]];
        p10 += vm * s;
    }
#pragma unroll
    for (int off = 16; off > 0; off >>= 1) {
        p9  += __shfl_down_sync(0xffffffffu, p9, off);
        p10 += __shfl_down_sync(0xffffffffu, p10, off);
    }
    if ((t & 31) == 0) { atomicAdd(&acc9, p9); atomicAdd(&acc10, p10); }
    __syncthreads();
    if (t == 0) { g_diag[8 * NN + i] = vi * acc9; g_diag[9 * NN + i] = vi * acc10; }
}

// diag(P^{p+8})[i] = sum_t C_p[t,i] * C_8[i,t], p = 3..8 (k = 11..16).
// C_8 tile staged/transposed in smem; C_p read coalesced (fp16 p<=7).
__global__ void __launch_bounds__(256) k_pair() {
    int i0 = blockIdx.x * 32;
    int t0 = blockIdx.y * 32;
    int tx = threadIdx.x;   // 0..31
    int ty = threadIdx.y;   // 0..7

    __shared__ float Bs[32][33];
#pragma unroll
    for (int q = 0; q < 4; q++) {
        int r = ty + 8 * q;
        Bs[r][tx] = g_C8[(size_t)(i0 + r) * NN + t0 + tx];
    }
    __syncthreads();

    float part[6];
#pragma unroll
    for (int j = 0; j < 6; j++) {                      // j -> power p = j+3
        float p = 0.f;
#pragma unroll
        for (int q = 0; q < 4; q++) {
            int tt = ty + 8 * q;
            float a = (j < 5)
                ? __half2float(g_Ch[j][(size_t)(t0 + tt) * NN + i0 + tx])
                : g_C8[(size_t)(t0 + tt) * NN + i0 + tx];
            p += a * Bs[tx][tt];
        }
        part[j] = p;
    }

    __shared__ float red[8][32];
#pragma unroll
    for (int j = 0; j < 6; j++) {
        __syncthreads();
        red[ty][tx] = part[j];
        __syncthreads();
        if (ty == 0) {
            float s = red[0][tx] + red[1][tx] + red[2][tx] + red[3][tx]
                    + red[4][tx] + red[5][tx] + red[6][tx] + red[7][tx];
            atomicAdd(&g_diag[(j + 10) * NN + i0 + tx], s);
        }
    }
}

// out[i][d] = b[d] + sum_k diag_k[i] * w[d][k]
__global__ void k_linear(const float* __restrict__ w, const float* __restrict__ b,
                         float* __restrict__ out) {
    int i = blockIdx.x * blockDim.x + threadIdx.x;
    if (i >= NN) return;
    float dv[WL];
#pragma unroll
    for (int k = 0; k < WL; k++) dv[k] = g_diag[k * NN + i];
#pragma unroll
    for (int d = 0; d < OD; d++) {
        float s = b[d];
#pragma unroll
        for (int k = 0; k < WL; k++) s += dv[k] * w[d * WL + k];
        out[i * OD + d] = s;
    }
}

extern "C" void kernel_launch(void* const* d_in, const int* in_sizes, int n_in,
                              void* d_out, int out_size) {
    const int* ei_raw = (const int*)d_in[0];           // edge_index [2, E]
    int E = in_sizes[0] / 2;
    if (E > EE) E = EE;

    const float* w = nullptr;
    const float* b = nullptr;
    for (int i = 1; i < n_in; i++) {
        if (in_sizes[i] == OD * WL)      w = (const float*)d_in[i];
        else if (in_sizes[i] == OD)      b = (const float*)d_in[i];
    }
    if (!w) w = (const float*)d_in[n_in - 2];
    if (!b) b = (const float*)d_in[n_in - 1];

    float* out = (float*)d_out;                        // [N, 8] fp32

    int init_elems = 2 * E > WL * NN ? 2 * E : WL * NN;
    k_init<<<(init_elems + 255) / 256, 256>>>(ei_raw, E);
    k_scatter<<<(E + 255) / 256, 256>>>(E);
    k_build_c3<<<NN, 256>>>();
    for (int p = 4; p <= 8; p++)                        // k_spmm(4) = launch #4
        k_spmm<<<NN, 256>>>(p);
    k_diag12<<<NN / 8, 256>>>();
    k_pair_sparse<<<NN, 256>>>();
    dim3 bb(32, 8), gg(NN / 32, NN / 32);
    k_pair<<<gg, bb>>>();
    k_linear<<<NN / 256, 256>>>(w, b, out);
}

// round 8
// speedup vs baseline: 1.3880x; 1.1034x over previous
#include <cuda_runtime.h>
#include <cuda_bf16.h>
#include <cuda_fp16.h>

// RWSE encoder: diag(P^k) for k=1..16, then linear [16 -> 8].
// P = D^{-1} A, sparse (E=65536 edges over N=4096 nodes).
//
//   C_p := (P^T)^p stored fp16 for p = 3..8 (g_Ch[p-3], 32 MB each).
//   C_3 by flattened 3-hop sparse scatter; C_4..C_8 by 5 gather-SpMM steps
//   (fp16 in, fp32 accum).  diag(P^p), p=3..8 extracted from fp32 accums
//   pre-quantization.  k=1,2 sparse direct; k=9,10 sparse walks vs C_8 rows;
//   k=11..16: diag(P^{p+8})[i] = sum_t C_p[t,i]*C_8[i,t], p=3..8.
//   out = diag @ w^T + b.

#define NN 4096
#define EE 65536
#define NSLOT 128
#define N2CAP 1024
#define WL 16
#define OD 8

// ---- static device scratch (no allocations allowed) ----
__device__ __half g_Ch[6][(size_t)NN * NN];  // 192 MB: C_3..C_8 (p -> g_Ch[p-3])
__device__ int    g_ei32[2 * EE];
__device__ int    g_degout[NN];
__device__ float  g_vdeg[NN];                // 1/max(degout,1)
__device__ int    g_cnt[NN];                 // in-edge counts  (by dest)
__device__ int    g_ocnt[NN];                // out-edge counts (by src)
__device__ int    g_src[NN * NSLOT];         // in-edge src lists
__device__ int    g_odst[NN * NSLOT];        // out-edge dst lists
__device__ float  g_diag[WL * NN];           // diag[k-1][i], fp32

// Fused: edge_index canonicalization (int32/int64 auto-detect) + zeroing.
__global__ void k_init(const int* __restrict__ raw, int E) {
    int acc = 0;
#pragma unroll
    for (int q = 1; q < 128; q += 2) acc |= raw[q];
    bool is64 = (acc == 0);
    int e = blockIdx.x * blockDim.x + threadIdx.x;
    if (e < 2 * E)
        g_ei32[e] = is64 ? (int)(((const long long*)raw)[e]) : raw[e];
    if (e < WL * NN) g_diag[e] = 0.0f;
    if (e < NN) { g_cnt[e] = 0; g_ocnt[e] = 0; g_degout[e] = 0; }
}

// Degree counting + adjacency-list build in one pass.
__global__ void k_scatter(int E) {
    int e = blockIdx.x * blockDim.x + threadIdx.x;
    if (e >= E) return;
    int r = g_ei32[e];
    int c = g_ei32[E + e];
    if (r < 0 || r >= NN || c < 0 || c >= NN) return;
    atomicAdd(&g_degout[r], 1);
    int p = atomicAdd(&g_cnt[c], 1);
    if (p < NSLOT) g_src[c * NSLOT + p] = r;
    int q = atomicAdd(&g_ocnt[r], 1);
    if (q < NSLOT) g_odst[r * NSLOT + q] = c;
}

// Precompute 1/deg once (avoids a divide per atomic in build_c3 / spmm).
__global__ void k_vdeg() {
    int i = blockIdx.x * blockDim.x + threadIdx.x;
    if (i < NN) {
        int d = g_degout[i]; if (d < 1) d = 1;
        g_vdeg[i] = 1.0f / (float)d;
    }
}

// C_3[c][m] via flattened 3-hop scatter. Phase A expands ~256 (r2, v12)
// 2-hop entries into smem; phase B: warp-per-entry, lanes over hop-3 edges.
__global__ void __launch_bounds__(256) k_build_c3() {
    __shared__ float srow[NN];
    __shared__ int   s_r2[N2CAP];
    __shared__ float s_v12[N2CAP];
    __shared__ int   s_n2;
    int c = blockIdx.x, t = threadIdx.x;
    float4* sz = (float4*)srow;
    for (int q = t; q < NN / 4; q += 256) sz[q] = make_float4(0.f, 0.f, 0.f, 0.f);
    if (t == 0) s_n2 = 0;
    __syncthreads();

    int n1 = g_cnt[c]; if (n1 > NSLOT) n1 = NSLOT;
    if (t < n1) {
        int r1 = g_src[c * NSLOT + t];
        float v1 = g_vdeg[r1];
        int n2 = g_cnt[r1]; if (n2 > NSLOT) n2 = NSLOT;
        int base = atomicAdd(&s_n2, n2);
        for (int e2 = 0; e2 < n2; e2++) {
            int idx = base + e2;
            if (idx < N2CAP) {
                int r2 = g_src[r1 * NSLOT + e2];
                s_r2[idx] = r2;
                s_v12[idx] = v1 * g_vdeg[r2];
            }
        }
    }
    __syncthreads();

    int n2h = s_n2; if (n2h > N2CAP) n2h = N2CAP;
    int w = t >> 5, lane = t & 31;
    for (int e = w; e < n2h; e += 8) {
        int r2 = s_r2[e];
        float v12 = s_v12[e];
        int n3 = g_cnt[r2]; if (n3 > NSLOT) n3 = NSLOT;
        for (int e3 = lane; e3 < n3; e3 += 32) {
            int r3 = g_src[r2 * NSLOT + e3];
            atomicAdd(&srow[r3], v12 * g_vdeg[r3]);
        }
    }
    __syncthreads();

    if (t == 0) g_diag[2 * NN + c] = srow[c];        // diag(P^3)
    uint4* o = (uint4*)(g_Ch[0] + (size_t)c * NN);
    const float4* s4 = (const float4*)srow;
    for (int q = t; q < NN / 8; q += 256) {
        float4 f0 = s4[2 * q], f1 = s4[2 * q + 1];
        __half2 hh[4];
        hh[0] = __floats2half2_rn(f0.x, f0.y);
        hh[1] = __floats2half2_rn(f0.z, f0.w);
        hh[2] = __floats2half2_rn(f1.x, f1.y);
        hh[3] = __floats2half2_rn(f1.z, f1.w);
        o[q] = *(uint4*)hh;
    }
}

// SpMM: C_p[c][:] = sum_{(r->c)} v * C_{p-1}[r][:].  fp16 gather, fp32 accum.
// Thread t owns columns [8t,8t+8) and [2048+8t, 2048+8t+8).
__global__ void __launch_bounds__(256) k_spmm(int p) {
    const __half* __restrict__ in = g_Ch[p - 4];
    int c = blockIdx.x;
    int t = threadIdx.x;

    __shared__ int   s_src[NSLOT];
    __shared__ float s_val[NSLOT];
    int n = g_cnt[c]; if (n > NSLOT) n = NSLOT;
    if (t < n) {
        int r = g_src[c * NSLOT + t];
        s_src[t] = r;
        s_val[t] = g_vdeg[r];
    }
    __syncthreads();

    float acc[16];
#pragma unroll
    for (int s = 0; s < 16; s++) acc[s] = 0.0f;

#pragma unroll 2
    for (int e = 0; e < n; e++) {
        const uint4* row = (const uint4*)(in + (size_t)s_src[e] * NN);
        float v = s_val[e];
        uint4 u0 = __ldg(row + t);
        uint4 u1 = __ldg(row + t + 256);
        const __half2* h0 = (const __half2*)&u0;
        const __half2* h1 = (const __half2*)&u1;
#pragma unroll
        for (int q = 0; q < 4; q++) {
            float2 f0 = __half22float2(h0[q]);
            float2 f1 = __half22float2(h1[q]);
            acc[2 * q]         += v * f0.x;
            acc[2 * q + 1]     += v * f0.y;
            acc[8 + 2 * q]     += v * f1.x;
            acc[8 + 2 * q + 1] += v * f1.y;
        }
    }

    int base0 = 8 * t, base1 = 2048 + 8 * t;
    if (c >= base0 && c < base0 + 8)
        g_diag[(p - 1) * NN + c] = acc[c - base0];
    if (c >= base1 && c < base1 + 8)
        g_diag[(p - 1) * NN + c] = acc[8 + (c - base1)];

    __half2 hh[8];
#pragma unroll
    for (int q = 0; q < 4; q++) {
        hh[q]     = __floats2half2_rn(acc[2 * q],     acc[2 * q + 1]);
        hh[4 + q] = __floats2half2_rn(acc[8 + 2 * q], acc[8 + 2 * q + 1]);
    }
    uint4* o = (uint4*)(g_Ch[p - 3] + (size_t)c * NN);
    o[t]       = *(uint4*)&hh[0];
    o[t + 256] = *(uint4*)&hh[4];
}

// diag(P^1)[i] = v_i * mult(i->i);  diag(P^2)[i] = v_i * sum_m v_m *
// mult(i->m) * [m in in(i)]. One warp per node.
__global__ void k_diag12() {
    int i = blockIdx.x * 8 + (threadIdx.x >> 5);
    int lane = threadIdx.x & 31;
    if (i >= NN) return;
    float vi = g_vdeg[i];
    int no = g_ocnt[i]; if (no > NSLOT) no = NSLOT;
    int ni = g_cnt[i];  if (ni > NSLOT) ni = NSLOT;

    float d1 = 0.f, d2 = 0.f;
    for (int e = lane; e < no; e += 32)
        if (g_odst[i * NSLOT + e] == i) d1 += 1.0f;
    for (int e2 = lane; e2 < ni; e2 += 32) {
        int m = g_src[i * NSLOT + e2];
        int cnt = 0;
        for (int e1 = 0; e1 < no; e1++)
            if (g_odst[i * NSLOT + e1] == m) cnt++;
        d2 += g_vdeg[m] * (float)cnt;
    }
#pragma unroll
    for (int off = 16; off > 0; off >>= 1) {
        d1 += __shfl_down_sync(0xffffffffu, d1, off);
        d2 += __shfl_down_sync(0xffffffffu, d2, off);
    }
    if (lane == 0) {
        g_diag[i] = vi * d1;
        g_diag[NN + i] = vi * d2;
    }
}

// k=9, k=10 via sparse walks against C_8's row i (fp16 -> fp32 smem).
__global__ void __launch_bounds__(256) k_pair_sparse() {
    __shared__ float srow[NN];
    __shared__ float acc9, acc10;
    int i = blockIdx.x, t = threadIdx.x;
    const __half2* c8 = (const __half2*)(g_Ch[5] + (size_t)i * NN);
    float2* s2 = (float2*)srow;
    for (int q = t; q < NN / 2; q += 256) s2[q] = __half22float2(c8[q]);
    if (t == 0) { acc9 = 0.f; acc10 = 0.f; }
    __syncthreads();

    float vi = g_vdeg[i];
    int no = g_ocnt[i]; if (no > NSLOT) no = NSLOT;

    float p9 = 0.f, p10 = 0.f;
    for (int e1 = t; e1 < no; e1 += 256) p9 += srow[g_odst[i * NSLOT + e1]];
    for (int e1 = 0; e1 < no; e1++) {
        int m = g_odst[i * NSLOT + e1];
        float vm = g_vdeg[m];
        int nm = g_ocnt[m]; if (nm > NSLOT) nm = NSLOT;
        float s = 0.f;
        for (int e2 = t; e2 < nm; e2 += 256) s += srow[g_odst[m * NSLOT + e2]];
        p10 += vm * s;
    }
#pragma unroll
    for (int off = 16; off > 0; off >>= 1) {
        p9  += __shfl_down_sync(0xffffffffu, p9, off);
        p10 += __shfl_down_sync(0xffffffffu, p10, off);
    }
    if ((t & 31) == 0) { atomicAdd(&acc9, p9); atomicAdd(&acc10, p10); }
    __syncthreads();
    if (t == 0) { g_diag[8 * NN + i] = vi * acc9; g_diag[9 * NN + i] = vi * acc10; }
}

// diag(P^{p+8})[i] = sum_t C_p[t,i] * C_8[i,t], p = 3..8 (k = 11..16).
// C_8 tile staged/transposed in smem; all matrices fp16 coalesced reads.
// Single-sync reduction: warp j (<6) reduces power p=j+3.
__global__ void __launch_bounds__(256) k_pair() {
    int i0 = blockIdx.x * 32;
    int t0 = blockIdx.y * 32;
    int tx = threadIdx.x;   // 0..31
    int ty = threadIdx.y;   // 0..7 (= warp id)

    __shared__ float Bs[32][33];
#pragma unroll
    for (int q = 0; q < 4; q++) {
        int r = ty + 8 * q;
        Bs[r][tx] = __half2float(g_Ch[5][(size_t)(i0 + r) * NN + t0 + tx]);
    }
    __syncthreads();

    __shared__ float red[6][8][33];
#pragma unroll
    for (int j = 0; j < 6; j++) {                      // j -> power p = j+3
        float p = 0.f;
#pragma unroll
        for (int q = 0; q < 4; q++) {
            int tt = ty + 8 * q;
            p += __half2float(g_Ch[j][(size_t)(t0 + tt) * NN + i0 + tx]) * Bs[tx][tt];
        }
        red[j][ty][tx] = p;
    }
    __syncthreads();

    if (ty < 6) {
        float s = red[ty][0][tx] + red[ty][1][tx] + red[ty][2][tx] + red[ty][3][tx]
                + red[ty][4][tx] + red[ty][5][tx] + red[ty][6][tx] + red[ty][7][tx];
        atomicAdd(&g_diag[(ty + 10) * NN + i0 + tx], s);
    }
}

// out[i][d] = b[d] + sum_k diag_k[i] * w[d][k]
__global__ void k_linear(const float* __restrict__ w, const float* __restrict__ b,
                         float* __restrict__ out) {
    int i = blockIdx.x * blockDim.x + threadIdx.x;
    if (i >= NN) return;
    float dv[WL];
#pragma unroll
    for (int k = 0; k < WL; k++) dv[k] = g_diag[k * NN + i];
#pragma unroll
    for (int d = 0; d < OD; d++) {
        float s = b[d];
#pragma unroll
        for (int k = 0; k < WL; k++) s += dv[k] * w[d * WL + k];
        out[i * OD + d] = s;
    }
}

extern "C" void kernel_launch(void* const* d_in, const int* in_sizes, int n_in,
                              void* d_out, int out_size) {
    const int* ei_raw = (const int*)d_in[0];           // edge_index [2, E]
    int E = in_sizes[0] / 2;
    if (E > EE) E = EE;

    const float* w = nullptr;
    const float* b = nullptr;
    for (int i = 1; i < n_in; i++) {
        if (in_sizes[i] == OD * WL)      w = (const float*)d_in[i];
        else if (in_sizes[i] == OD)      b = (const float*)d_in[i];
    }
    if (!w) w = (const float*)d_in[n_in - 2];
    if (!b) b = (const float*)d_in[n_in - 1];

    float* out = (float*)d_out;                        // [N, 8] fp32

    int init_elems = 2 * E > WL * NN ? 2 * E : WL * NN;
    k_init<<<(init_elems + 255) / 256, 256>>>(ei_raw, E);
    k_scatter<<<(E + 255) / 256, 256>>>(E);
    k_vdeg<<<NN / 256, 256>>>();
    k_build_c3<<<NN, 256>>>();                          // launch #4 -> profiled
    for (int p = 4; p <= 8; p++)
        k_spmm<<<NN, 256>>>(p);
    k_diag12<<<NN / 8, 256>>>();
    k_pair_sparse<<<NN, 256>>>();
    dim3 bb(32, 8), gg(NN / 32, NN / 32);
    k_pair<<<gg, bb>>>();
    k_linear<<<NN / 256, 256>>>(w, b, out);
}

// round 9
// speedup vs baseline: 1.6588x; 1.1951x over previous
#include <cuda_runtime.h>
#include <cuda_bf16.h>
#include <cuda_fp16.h>

// RWSE encoder: diag(P^k) for k=1..16, then linear [16 -> 8].
// P = D^{-1} A, sparse (E=65536 edges over N=4096 nodes).
//
//   C_p := (P^T)^p stored fp16 for p = 2..8 (g_Ch[p-2], 32 MB each).
//   C_2 by flat 2-hop sparse scatter (1M smem atomics); C_3..C_8 by 6
//   gather-SpMM steps (fp16 in, fp32 accum).  diag(P^p) extracted from the
//   fp32 accumulators BEFORE quantization (p=2 from the smem row).
//   k=1 sparse direct; k=9,10 sparse walks vs C_8 rows; k=11..16:
//   diag(P^{p+8})[i] = sum_t C_p[t,i]*C_8[i,t], p=3..8.
//   out = diag @ w^T + b.

#define NN 4096
#define EE 65536
#define NSLOT 128
#define WL 16
#define OD 8

// ---- static device scratch (no allocations allowed) ----
__device__ __half g_Ch[7][(size_t)NN * NN];  // 224 MB: C_2..C_8 (p -> g_Ch[p-2])
__device__ int    g_ei32[2 * EE];
__device__ int    g_degout[NN];
__device__ float  g_vdeg[NN];                // 1/max(degout,1)
__device__ int    g_cnt[NN];                 // in-edge counts  (by dest)
__device__ int    g_ocnt[NN];                // out-edge counts (by src)
__device__ int    g_src[NN * NSLOT];         // in-edge src lists
__device__ int    g_odst[NN * NSLOT];        // out-edge dst lists
__device__ float  g_diag[WL * NN];           // diag[k-1][i], fp32

// Fused: edge_index canonicalization (int32/int64 auto-detect) + zeroing.
__global__ void k_init(const int* __restrict__ raw, int E) {
    int acc = 0;
#pragma unroll
    for (int q = 1; q < 128; q += 2) acc |= raw[q];
    bool is64 = (acc == 0);
    int e = blockIdx.x * blockDim.x + threadIdx.x;
    if (e < 2 * E)
        g_ei32[e] = is64 ? (int)(((const long long*)raw)[e]) : raw[e];
    if (e < WL * NN) g_diag[e] = 0.0f;
    if (e < NN) { g_cnt[e] = 0; g_ocnt[e] = 0; g_degout[e] = 0; }
}

// Degree counting + adjacency-list build in one pass.
__global__ void k_scatter(int E) {
    int e = blockIdx.x * blockDim.x + threadIdx.x;
    if (e >= E) return;
    int r = g_ei32[e];
    int c = g_ei32[E + e];
    if (r < 0 || r >= NN || c < 0 || c >= NN) return;
    atomicAdd(&g_degout[r], 1);
    int p = atomicAdd(&g_cnt[c], 1);
    if (p < NSLOT) g_src[c * NSLOT + p] = r;
    int q = atomicAdd(&g_ocnt[r], 1);
    if (q < NSLOT) g_odst[r * NSLOT + q] = c;
}

// Precompute 1/deg once.
__global__ void k_vdeg() {
    int i = blockIdx.x * blockDim.x + threadIdx.x;
    if (i < NN) {
        int d = g_degout[i]; if (d < 1) d = 1;
        g_vdeg[i] = 1.0f / (float)d;
    }
}

// C_2[c][m] = sum_{(r->c)} v_r * sum_{(m->r)} v_m via flat 2-hop scatter:
// thread t handles hop-1 edge t (deg ~16 => ~16 active threads, ~256 smem
// atomics per block, 1M total). diag(P^2) taken from fp32 row pre-quant.
__global__ void __launch_bounds__(256) k_build_c2() {
    __shared__ float srow[NN];
    int c = blockIdx.x, t = threadIdx.x;
    float4* sz = (float4*)srow;
    for (int q = t; q < NN / 4; q += 256) sz[q] = make_float4(0.f, 0.f, 0.f, 0.f);
    __syncthreads();

    int n1 = g_cnt[c]; if (n1 > NSLOT) n1 = NSLOT;
    if (t < n1) {
        int r1 = g_src[c * NSLOT + t];
        float v1 = g_vdeg[r1];
        int n2 = g_cnt[r1]; if (n2 > NSLOT) n2 = NSLOT;
        for (int e2 = 0; e2 < n2; e2++) {
            int r2 = g_src[r1 * NSLOT + e2];
            atomicAdd(&srow[r2], v1 * g_vdeg[r2]);
        }
    }
    __syncthreads();

    if (t == 0) g_diag[NN + c] = srow[c];            // diag(P^2)
    uint4* o = (uint4*)(g_Ch[0] + (size_t)c * NN);
    const float4* s4 = (const float4*)srow;
    for (int q = t; q < NN / 8; q += 256) {
        float4 f0 = s4[2 * q], f1 = s4[2 * q + 1];
        __half2 hh[4];
        hh[0] = __floats2half2_rn(f0.x, f0.y);
        hh[1] = __floats2half2_rn(f0.z, f0.w);
        hh[2] = __floats2half2_rn(f1.x, f1.y);
        hh[3] = __floats2half2_rn(f1.z, f1.w);
        o[q] = *(uint4*)hh;
    }
}

// SpMM: C_p[c][:] = sum_{(r->c)} v * C_{p-1}[r][:].  fp16 gather, fp32 accum.
// Thread t owns columns [8t,8t+8) and [2048+8t, 2048+8t+8).
__global__ void __launch_bounds__(256) k_spmm(int p) {
    const __half* __restrict__ in = g_Ch[p - 3];
    int c = blockIdx.x;
    int t = threadIdx.x;

    __shared__ int   s_src[NSLOT];
    __shared__ float s_val[NSLOT];
    int n = g_cnt[c]; if (n > NSLOT) n = NSLOT;
    if (t < n) {
        int r = g_src[c * NSLOT + t];
        s_src[t] = r;
        s_val[t] = g_vdeg[r];
    }
    __syncthreads();

    float acc[16];
#pragma unroll
    for (int s = 0; s < 16; s++) acc[s] = 0.0f;

#pragma unroll 2
    for (int e = 0; e < n; e++) {
        const uint4* row = (const uint4*)(in + (size_t)s_src[e] * NN);
        float v = s_val[e];
        uint4 u0 = __ldg(row + t);
        uint4 u1 = __ldg(row + t + 256);
        const __half2* h0 = (const __half2*)&u0;
        const __half2* h1 = (const __half2*)&u1;
#pragma unroll
        for (int q = 0; q < 4; q++) {
            float2 f0 = __half22float2(h0[q]);
            float2 f1 = __half22float2(h1[q]);
            acc[2 * q]         += v * f0.x;
            acc[2 * q + 1]     += v * f0.y;
            acc[8 + 2 * q]     += v * f1.x;
            acc[8 + 2 * q + 1] += v * f1.y;
        }
    }

    int base0 = 8 * t, base1 = 2048 + 8 * t;
    if (c >= base0 && c < base0 + 8)
        g_diag[(p - 1) * NN + c] = acc[c - base0];
    if (c >= base1 && c < base1 + 8)
        g_diag[(p - 1) * NN + c] = acc[8 + (c - base1)];

    __half2 hh[8];
#pragma unroll
    for (int q = 0; q < 4; q++) {
        hh[q]     = __floats2half2_rn(acc[2 * q],     acc[2 * q + 1]);
        hh[4 + q] = __floats2half2_rn(acc[8 + 2 * q], acc[8 + 2 * q + 1]);
    }
    uint4* o = (uint4*)(g_Ch[p - 2] + (size_t)c * NN);
    o[t]       = *(uint4*)&hh[0];
    o[t + 256] = *(uint4*)&hh[4];
}

// diag(P^1)[i] = v_i * mult(i->i). One warp per node.
__global__ void k_diag1() {
    int i = blockIdx.x * 8 + (threadIdx.x >> 5);
    int lane = threadIdx.x & 31;
    if (i >= NN) return;
    int no = g_ocnt[i]; if (no > NSLOT) no = NSLOT;
    float d1 = 0.f;
    for (int e = lane; e < no; e += 32)
        if (g_odst[i * NSLOT + e] == i) d1 += 1.0f;
#pragma unroll
    for (int off = 16; off > 0; off >>= 1)
        d1 += __shfl_down_sync(0xffffffffu, d1, off);
    if (lane == 0) g_diag[i] = g_vdeg[i] * d1;
}

// k=9, k=10 via sparse walks against C_8's row i (fp16 -> fp32 smem).
__global__ void __launch_bounds__(256) k_pair_sparse() {
    __shared__ float srow[NN];
    __shared__ float acc9, acc10;
    int i = blockIdx.x, t = threadIdx.x;
    const __half2* c8 = (const __half2*)(g_Ch[6] + (size_t)i * NN);
    float2* s2 = (float2*)srow;
    for (int q = t; q < NN / 2; q += 256) s2[q] = __half22float2(c8[q]);
    if (t == 0) { acc9 = 0.f; acc10 = 0.f; }
    __syncthreads();

    float vi = g_vdeg[i];
    int no = g_ocnt[i]; if (no > NSLOT) no = NSLOT;

    float p9 = 0.f, p10 = 0.f;
    for (int e1 = t; e1 < no; e1 += 256) p9 += srow[g_odst[i * NSLOT + e1]];
    for (int e1 = 0; e1 < no; e1++) {
        int m = g_odst[i * NSLOT + e1];
        float vm = g_vdeg[m];
        int nm = g_ocnt[m]; if (nm > NSLOT) nm = NSLOT;
        float s = 0.f;
        for (int e2 = t; e2 < nm; e2 += 256) s += srow[g_odst[m * NSLOT + e2]];
        p10 += vm * s;
    }
#pragma unroll
    for (int off = 16; off > 0; off >>= 1) {
        p9  += __shfl_down_sync(0xffffffffu, p9, off);
        p10 += __shfl_down_sync(0xffffffffu, p10, off);
    }
    if ((t & 31) == 0) { atomicAdd(&acc9, p9); atomicAdd(&acc10, p10); }
    __syncthreads();
    if (t == 0) { g_diag[8 * NN + i] = vi * acc9; g_diag[9 * NN + i] = vi * acc10; }
}

// diag(P^{p+8})[i] = sum_t C_p[t,i] * C_8[i,t], p = 3..8 (k = 11..16).
// C_8 tile staged/transposed in smem; single-sync reduction (warp j -> p=j+3).
__global__ void __launch_bounds__(256) k_pair() {
    int i0 = blockIdx.x * 32;
    int t0 = blockIdx.y * 32;
    int tx = threadIdx.x;   // 0..31
    int ty = threadIdx.y;   // 0..7 (= warp id)

    __shared__ float Bs[32][33];
#pragma unroll
    for (int q = 0; q < 4; q++) {
        int r = ty + 8 * q;
        Bs[r][tx] = __half2float(g_Ch[6][(size_t)(i0 + r) * NN + t0 + tx]);
    }
    __syncthreads();

    __shared__ float red[6][8][33];
#pragma unroll
    for (int j = 0; j < 6; j++) {                      // j -> power p = j+3
        float p = 0.f;
#pragma unroll
        for (int q = 0; q < 4; q++) {
            int tt = ty + 8 * q;
            p += __half2float(g_Ch[j + 1][(size_t)(t0 + tt) * NN + i0 + tx]) * Bs[tx][tt];
        }
        red[j][ty][tx] = p;
    }
    __syncthreads();

    if (ty < 6) {
        float s = red[ty][0][tx] + red[ty][1][tx] + red[ty][2][tx] + red[ty][3][tx]
                + red[ty][4][tx] + red[ty][5][tx] + red[ty][6][tx] + red[ty][7][tx];
        atomicAdd(&g_diag[(ty + 10) * NN + i0 + tx], s);
    }
}

// out[i][d] = b[d] + sum_k diag_k[i] * w[d][k]
__global__ void k_linear(const float* __restrict__ w, const float* __restrict__ b,
                         float* __restrict__ out) {
    int i = blockIdx.x * blockDim.x + threadIdx.x;
    if (i >= NN) return;
    float dv[WL];
#pragma unroll
    for (int k = 0; k < WL; k++) dv[k] = g_diag[k * NN + i];
#pragma unroll
    for (int d = 0; d < OD; d++) {
        float s = b[d];
#pragma unroll
        for (int k = 0; k < WL; k++) s += dv[k] * w[d * WL + k];
        out[i * OD + d] = s;
    }
}

extern "C" void kernel_launch(void* const* d_in, const int* in_sizes, int n_in,
                              void* d_out, int out_size) {
    const int* ei_raw = (const int*)d_in[0];           // edge_index [2, E]
    int E = in_sizes[0] / 2;
    if (E > EE) E = EE;

    const float* w = nullptr;
    const float* b = nullptr;
    for (int i = 1; i < n_in; i++) {
        if (in_sizes[i] == OD * WL)      w = (const float*)d_in[i];
        else if (in_sizes[i] == OD)      b = (const float*)d_in[i];
    }
    if (!w) w = (const float*)d_in[n_in - 2];
    if (!b) b = (const float*)d_in[n_in - 1];

    float* out = (float*)d_out;                        // [N, 8] fp32

    int init_elems = 2 * E > WL * NN ? 2 * E : WL * NN;
    k_init<<<(init_elems + 255) / 256, 256>>>(ei_raw, E);
    k_scatter<<<(E + 255) / 256, 256>>>(E);
    k_vdeg<<<NN / 256, 256>>>();
    k_build_c2<<<NN, 256>>>();                          // launch #4 -> profiled
    for (int p = 3; p <= 8; p++)
        k_spmm<<<NN, 256>>>(p);
    k_diag1<<<NN / 8, 256>>>();
    k_pair_sparse<<<NN, 256>>>();
    dim3 bb(32, 8), gg(NN / 32, NN / 32);
    k_pair<<<gg, bb>>>();
    k_linear<<<NN / 256, 256>>>(w, b, out);
}

// round 12
// speedup vs baseline: 1.8610x; 1.1219x over previous
#include <cuda_runtime.h>
#include <cuda_bf16.h>
#include <cuda_fp16.h>

// RWSE encoder: diag(P^k) for k=1..16, then linear [16 -> 8].
// P = D^{-1} A, sparse (E=65536 edges over N=4096 nodes).
//
//   C_p := (P^T)^p stored fp16 for p = 2..8 (g_Ch[p-2], 32 MB each).
//   C_2 by flat 2-hop sparse scatter (warp/e1, lane/e2); C_3..C_8 by 6
//   gather-SpMM steps (fp16 in, fp32 accum).  diag(P^p) extracted from fp32
//   accums BEFORE quantization (p=2 from the smem row).  k=1 sparse direct.
//   k=9..16 via one pairing kernel: diag(P^{a+b})[i] = sum_t C_a[t,i]*C_b[i,t]
//   with (a,b) = (4,5),(5,5),(3,8),(4,8),(5,8),(6,8),(7,8),(8,8).
//   out = diag @ w^T + b.

#define NN 4096
#define EE 65536
#define NSLOT 128
#define WL 16
#define OD 8

// ---- static device scratch (no allocations allowed) ----
__device__ __half g_Ch[7][(size_t)NN * NN];  // 224 MB: C_2..C_8 (p -> g_Ch[p-2])
__device__ int    g_ei32[2 * EE];
__device__ int    g_degout[NN];
__device__ float  g_vdeg[NN];                // 1/max(degout,1)
__device__ int    g_cnt[NN];                 // in-edge counts  (by dest)
__device__ int    g_ocnt[NN];                // out-edge counts (by src)
__device__ int    g_src[NN * NSLOT];         // in-edge src lists
__device__ int    g_odst[NN * NSLOT];        // out-edge dst lists
__device__ float  g_diag[WL * NN];           // diag[k-1][i], fp32

// Fused: edge_index canonicalization (int32/int64 auto-detect) + zeroing.
__global__ void k_init(const int* __restrict__ raw, int E) {
    int acc = 0;
#pragma unroll
    for (int q = 1; q < 128; q += 2) acc |= raw[q];
    bool is64 = (acc == 0);
    int e = blockIdx.x * blockDim.x + threadIdx.x;
    if (e < 2 * E)
        g_ei32[e] = is64 ? (int)(((const long long*)raw)[e]) : raw[e];
    if (e < WL * NN) g_diag[e] = 0.0f;
    if (e < NN) { g_cnt[e] = 0; g_ocnt[e] = 0; g_degout[e] = 0; }
}

// Degree counting + adjacency-list build in one pass.
__global__ void k_scatter(int E) {
    int e = blockIdx.x * blockDim.x + threadIdx.x;
    if (e >= E) return;
    int r = g_ei32[e];
    int c = g_ei32[E + e];
    if (r < 0 || r >= NN || c < 0 || c >= NN) return;
    atomicAdd(&g_degout[r], 1);
    int p = atomicAdd(&g_cnt[c], 1);
    if (p < NSLOT) g_src[c * NSLOT + p] = r;
    int q = atomicAdd(&g_ocnt[r], 1);
    if (q < NSLOT) g_odst[r * NSLOT + q] = c;
}

// Fused vdeg + diag(P^1). Warp w of block b owns node i = 8b + w.
__global__ void k_prep() {
    int i = blockIdx.x * 8 + (threadIdx.x >> 5);
    int lane = threadIdx.x & 31;
    if (i >= NN) return;
    int d = g_degout[i]; if (d < 1) d = 1;
    float vi = 1.0f / (float)d;
    if (lane == 0) g_vdeg[i] = vi;
    int no = g_ocnt[i]; if (no > NSLOT) no = NSLOT;
    float d1 = 0.f;
    for (int e = lane; e < no; e += 32)
        if (g_odst[i * NSLOT + e] == i) d1 += 1.0f;
#pragma unroll
    for (int off = 16; off > 0; off >>= 1)
        d1 += __shfl_down_sync(0xffffffffu, d1, off);
    if (lane == 0) g_diag[i] = vi * d1;
}

// C_2[c][m] = sum_{(r->c)} v_r * sum_{(m->r)} v_m.  Flat 2-hop scatter:
// warp w covers hop-1 edges {w, w+8, ...}, lanes spread over hop-2 edges.
// diag(P^2) taken from the fp32 smem row pre-quantization.
__global__ void __launch_bounds__(256) k_build_c2() {
    __shared__ float srow[NN];
    int c = blockIdx.x, t = threadIdx.x;
    int w = t >> 5, lane = t & 31;
    float4* sz = (float4*)srow;
    for (int q = t; q < NN / 4; q += 256) sz[q] = make_float4(0.f, 0.f, 0.f, 0.f);
    __syncthreads();

    int n1 = g_cnt[c]; if (n1 > NSLOT) n1 = NSLOT;
    for (int e1 = w; e1 < n1; e1 += 8) {
        int r1 = g_src[c * NSLOT + e1];
        float v1 = g_vdeg[r1];
        int n2 = g_cnt[r1]; if (n2 > NSLOT) n2 = NSLOT;
        for (int e2 = lane; e2 < n2; e2 += 32) {
            int r2 = g_src[r1 * NSLOT + e2];
            atomicAdd(&srow[r2], v1 * g_vdeg[r2]);
        }
    }
    __syncthreads();

    if (t == 0) g_diag[NN + c] = srow[c];            // diag(P^2)
    uint4* o = (uint4*)(g_Ch[0] + (size_t)c * NN);
    const float4* s4 = (const float4*)srow;
    for (int q = t; q < NN / 8; q += 256) {
        float4 f0 = s4[2 * q], f1 = s4[2 * q + 1];
        __half2 hh[4];
        hh[0] = __floats2half2_rn(f0.x, f0.y);
        hh[1] = __floats2half2_rn(f0.z, f0.w);
        hh[2] = __floats2half2_rn(f1.x, f1.y);
        hh[3] = __floats2half2_rn(f1.z, f1.w);
        o[q] = *(uint4*)hh;
    }
}

// SpMM: C_p[c][:] = sum_{(r->c)} v * C_{p-1}[r][:].  fp16 gather, fp32 accum.
// Thread t owns columns [8t,8t+8) and [2048+8t, 2048+8t+8).
__global__ void __launch_bounds__(256) k_spmm(int p) {
    const __half* __restrict__ in = g_Ch[p - 3];
    int c = blockIdx.x;
    int t = threadIdx.x;

    __shared__ int   s_src[NSLOT];
    __shared__ float s_val[NSLOT];
    int n = g_cnt[c]; if (n > NSLOT) n = NSLOT;
    if (t < n) {
        int r = g_src[c * NSLOT + t];
        s_src[t] = r;
        s_val[t] = g_vdeg[r];
    }
    __syncthreads();

    float acc[16];
#pragma unroll
    for (int s = 0; s < 16; s++) acc[s] = 0.0f;

#pragma unroll 2
    for (int e = 0; e < n; e++) {
        const uint4* row = (const uint4*)(in + (size_t)s_src[e] * NN);
        float v = s_val[e];
        uint4 u0 = __ldg(row + t);
        uint4 u1 = __ldg(row + t + 256);
        const __half2* h0 = (const __half2*)&u0;
        const __half2* h1 = (const __half2*)&u1;
#pragma unroll
        for (int q = 0; q < 4; q++) {
            float2 f0 = __half22float2(h0[q]);
            float2 f1 = __half22float2(h1[q]);
            acc[2 * q]         += v * f0.x;
            acc[2 * q + 1]     += v * f0.y;
            acc[8 + 2 * q]     += v * f1.x;
            acc[8 + 2 * q + 1] += v * f1.y;
        }
    }

    int base0 = 8 * t, base1 = 2048 + 8 * t;
    if (c >= base0 && c < base0 + 8)
        g_diag[(p - 1) * NN + c] = acc[c - base0];
    if (c >= base1 && c < base1 + 8)
        g_diag[(p - 1) * NN + c] = acc[8 + (c - base1)];

    __half2 hh[8];
#pragma unroll
    for (int q = 0; q < 4; q++) {
        hh[q]     = __floats2half2_rn(acc[2 * q],     acc[2 * q + 1]);
        hh[4 + q] = __floats2half2_rn(acc[8 + 2 * q], acc[8 + 2 * q + 1]);
    }
    uint4* o = (uint4*)(g_Ch[p - 2] + (size_t)c * NN);
    o[t]       = *(uint4*)&hh[0];
    o[t + 256] = *(uint4*)&hh[4];
}

// All of k=9..16 in one pass: diag(P^{a+b})[i] = sum_t C_a[t,i] * C_b[i,t].
// (a,b) per output j (k=9+j): (4,5),(5,5),(3,8),(4,8),(5,8),(6,8),(7,8),(8,8).
// Two transposed B tiles staged in smem (C_5 and C_8); A-side loads of
// C_3..C_8 shared across outputs; single-sync reduction, warp j -> k=9+j.
__global__ void __launch_bounds__(256) k_pair() {
    int i0 = blockIdx.x * 32;
    int t0 = blockIdx.y * 32;
    int tx = threadIdx.x;   // 0..31
    int ty = threadIdx.y;   // 0..7 (= warp id)

    __shared__ float B5[32][33];
    __shared__ float B8[32][33];
#pragma unroll
    for (int q = 0; q < 4; q++) {
        int r = ty + 8 * q;
        B5[r][tx] = __half2float(g_Ch[3][(size_t)(i0 + r) * NN + t0 + tx]);
        B8[r][tx] = __half2float(g_Ch[6][(size_t)(i0 + r) * NN + t0 + tx]);
    }
    __syncthreads();

    float part[8];
#pragma unroll
    for (int j = 0; j < 8; j++) part[j] = 0.f;

#pragma unroll
    for (int q = 0; q < 4; q++) {
        int tt = ty + 8 * q;
        size_t off = (size_t)(t0 + tt) * NN + i0 + tx;
        float a3 = __half2float(g_Ch[1][off]);
        float a4 = __half2float(g_Ch[2][off]);
        float a5 = __half2float(g_Ch[3][off]);
        float a6 = __half2float(g_Ch[4][off]);
        float a7 = __half2float(g_Ch[5][off]);
        float a8 = __half2float(g_Ch[6][off]);
        float b5 = B5[tx][tt];
        float b8 = B8[tx][tt];
        part[0] += a4 * b5;      // k =  9 = 4+5
        part[1] += a5 * b5;      // k = 10 = 5+5
        part[2] += a3 * b8;      // k = 11 = 3+8
        part[3] += a4 * b8;      // k = 12 = 4+8
        part[4] += a5 * b8;      // k = 13 = 5+8
        part[5] += a6 * b8;      // k = 14 = 6+8
        part[6] += a7 * b8;      // k = 15 = 7+8
        part[7] += a8 * b8;      // k = 16 = 8+8
    }

    __shared__ float red[8][8][33];
#pragma unroll
    for (int j = 0; j < 8; j++) red[j][ty][tx] = part[j];
    __syncthreads();

    {
        float s = red[ty][0][tx] + red[ty][1][tx] + red[ty][2][tx] + red[ty][3][tx]
                + red[ty][4][tx] + red[ty][5][tx] + red[ty][6][tx] + red[ty][7][tx];
        atomicAdd(&g_diag[(8 + ty) * NN + i0 + tx], s);
    }
}

// out[i][d] = b[d] + sum_k diag_k[i] * w[d][k]
__global__ void k_linear(const float* __restrict__ w, const float* __restrict__ b,
                         float* __restrict__ out) {
    int i = blockIdx.x * blockDim.x + threadIdx.x;
    if (i >= NN) return;
    float dv[WL];
#pragma unroll
    for (int k = 0; k < WL; k++) dv[k] = g_diag[k * NN + i];
#pragma unroll
    for (int d = 0; d < OD; d++) {
        float s = b[d];
#pragma unroll
        for (int k = 0; k < WL; k++) s += dv[k] * w[d * WL + k];
        out[i * OD + d] = s;
    }
}

extern "C" void kernel_launch(void* const* d_in, const int* in_sizes, int n_in,
                              void* d_out, int out_size) {
    const int* ei_raw = (const int*)d_in[0];           // edge_index [2, E]
    int E = in_sizes[0] / 2;
    if (E > EE) E = EE;

    const float* w = nullptr;
    const float* b = nullptr;
    for (int i = 1; i < n_in; i++) {
        if (in_sizes[i] == OD * WL)      w = (const float*)d_in[i];
        else if (in_sizes[i] == OD)      b = (const float*)d_in[i];
    }
    if (!w) w = (const float*)d_in[n_in - 2];
    if (!b) b = (const float*)d_in[n_in - 1];

    float* out = (float*)d_out;                        // [N, 8] fp32

    int init_elems = 2 * E > WL * NN ? 2 * E : WL * NN;
    k_init<<<(init_elems + 255) / 256, 256>>>(ei_raw, E);
    k_scatter<<<(E + 255) / 256, 256>>>(E);
    k_prep<<<NN / 8, 256>>>();
    k_build_c2<<<NN, 256>>>();                          // launch #4 -> profiled
    for (int p = 3; p <= 8; p++)
        k_spmm<<<NN, 256>>>(p);
    dim3 bb(32, 8), gg(NN / 32, NN / 32);
    k_pair<<<gg, bb>>>();
    k_linear<<<NN / 256, 256>>>(w, b, out);
}